// round 16
// baseline (speedup 1.0000x reference)
#include <cuda_runtime.h>
#include <cuda_bf16.h>
#include <cstdint>

// Shapes (fixed by the problem): B=32, C=256, H=W=64
#define B_DIM 32
#define C_DIM 256
#define HW    4096            // 64*64
#define NTHREADS 256
#define CHUNKS 2              // 2 x 8 floats = 16 floats/thread; 256*16 = 4096

// TERMINAL KERNEL (session R2-R15). Validated model:
//   dur_us = max(~45.1us floor, kernel + ~4us replay overhead)
//   floor  = 268 MB compulsory DRAM traffic / ~5.93 TB/s sustained mixed-R/W.
// All alternatives bench-falsified:
//  - Cross-replay L2 residency: evict_last modifier (thrash at 134MB>126MB),
//    address-split partial pin (neutral), createpolicy fractional (inert),
//    .cs store exclusion (DRAM traffic unchanged) — persisting-L2 carve-out
//    is 0 and raising it violates harness device-limit rules.
//  - Store-stream shaping (.cs): does not move the DRAM wall.
//  - Width mismatch (v8 ld + v4 st): +5us mechanical penalty (R7/R10/R14).
// Best config = width-matched v8/v8, one CTA per (b,c) plane, plane fully
// register-resident (compulsory traffic only), single barrier, fused
// dtype-agnostic style-id decode. Measured: kernel 36.3-36.7us (DRAM ~73%),
// dur_us 45.088-45.12 (floor-bound).

__device__ __forceinline__ void ld_v8(const float* p, float* v) {
    unsigned r0, r1, r2, r3, r4, r5, r6, r7;
    asm volatile(
        "ld.global.v8.b32 {%0,%1,%2,%3,%4,%5,%6,%7}, [%8];"
        : "=r"(r0), "=r"(r1), "=r"(r2), "=r"(r3),
          "=r"(r4), "=r"(r5), "=r"(r6), "=r"(r7)
        : "l"(p));
    v[0] = __uint_as_float(r0); v[1] = __uint_as_float(r1);
    v[2] = __uint_as_float(r2); v[3] = __uint_as_float(r3);
    v[4] = __uint_as_float(r4); v[5] = __uint_as_float(r5);
    v[6] = __uint_as_float(r6); v[7] = __uint_as_float(r7);
}

__device__ __forceinline__ void st_v8(float* p, const float* v) {
    asm volatile(
        "st.global.v8.b32 [%0], {%1,%2,%3,%4,%5,%6,%7,%8};"
        :
        : "l"(p),
          "r"(__float_as_uint(v[0])), "r"(__float_as_uint(v[1])),
          "r"(__float_as_uint(v[2])), "r"(__float_as_uint(v[3])),
          "r"(__float_as_uint(v[4])), "r"(__float_as_uint(v[5])),
          "r"(__float_as_uint(v[6])), "r"(__float_as_uint(v[7]))
        : "memory");
}

// style_id may arrive as int64 (reference dtype) or int32 (JAX x64-off).
// Thread-0 per-CTA detection over the first 16 words (64 B, in-bounds for
// both layouts): int64 LE with ids in [0,16) => all odd words zero; int32 =>
// odd words random; false-positive prob 16^-8 ~ 2.3e-10.
__global__ __launch_bounds__(NTHREADS, 8)
void cond_inorm2d_kernel(const float* __restrict__ x,
                         const unsigned int* __restrict__ sid_raw,
                         const float* __restrict__ gamma,
                         const float* __restrict__ beta,
                         float* __restrict__ out) {
    const int plane = blockIdx.x;               // b*C + c, 0..8191
    const int b = plane >> 8;                   // C_DIM = 256
    const int c = plane & (C_DIM - 1);

    const float* __restrict__ xp = x   + (size_t)plane * HW;
    float* __restrict__       op = out + (size_t)plane * HW;

    const int t = threadIdx.x;

    __shared__ float sh_s[8];
    __shared__ float sh_s2[8];
    __shared__ int   sh_sid;

    // ---- Thread 0: decode style id (dtype-agnostic) ----
    if (t == 0) {
        unsigned int ored = 0u;
        for (int i = 1; i < 16; i += 2) ored |= sid_raw[i];
        sh_sid = (ored == 0u) ? (int)sid_raw[2 * b] : (int)sid_raw[b];
    }

    // ---- Load entire plane slice into registers; accumulate moments ----
    // Thread t owns 32-byte chunks at float offset (i*NTHREADS + t)*8;
    // fully coalesced, width-matched with the stores below.
    float vf[CHUNKS][8];
    float s = 0.f, s2 = 0.f;
#pragma unroll
    for (int i = 0; i < CHUNKS; i++) {
        ld_v8(xp + (size_t)(i * NTHREADS + t) * 8, vf[i]);
#pragma unroll
        for (int j = 0; j < 8; j++) {
            s  += vf[i][j];
            s2 += vf[i][j] * vf[i][j];
        }
    }

    // ---- Warp reduce ----
#pragma unroll
    for (int o = 16; o > 0; o >>= 1) {
        s  += __shfl_xor_sync(0xFFFFFFFFu, s,  o);
        s2 += __shfl_xor_sync(0xFFFFFFFFu, s2, o);
    }

    const int w = t >> 5, l = t & 31;
    if (l == 0) { sh_s[w] = s; sh_s2[w] = s2; }
    __syncthreads();   // single barrier: partials + sh_sid now visible

    // ---- Every warp redundantly reduces the 8 partials (no 2nd barrier) ----
    float a  = (l < 8) ? sh_s[l]  : 0.f;
    float a2 = (l < 8) ? sh_s2[l] : 0.f;
#pragma unroll
    for (int o = 4; o > 0; o >>= 1) {   // xor 4,2,1 stays within 8-lane group
        a  += __shfl_xor_sync(0xFFFFFFFFu, a,  o);
        a2 += __shfl_xor_sync(0xFFFFFFFFu, a2, o);
    }
    const float tot_s  = __shfl_sync(0xFFFFFFFFu, a,  0);
    const float tot_s2 = __shfl_sync(0xFFFFFFFFu, a2, 0);

    const float inv_n = 1.0f / (float)HW;
    const float mean  = tot_s * inv_n;
    const float var   = fmaxf(tot_s2 * inv_n - mean * mean, 0.0f);
    const float rstd  = rsqrtf(var + 1e-5f);

    const int sid = sh_sid;
    const float g  = gamma[sid * C_DIM + c];
    const float be = beta[sid * C_DIM + c];
    const float sc = g * rstd;
    const float sf = be - mean * sc;     // out = x*sc + sf

    // ---- Normalize from registers and store (width-matched 256-bit) ----
#pragma unroll
    for (int i = 0; i < CHUNKS; i++) {
        float o8[8];
#pragma unroll
        for (int j = 0; j < 8; j++) o8[j] = vf[i][j] * sc + sf;
        st_v8(op + (size_t)(i * NTHREADS + t) * 8, o8);
    }
}

extern "C" void kernel_launch(void* const* d_in, const int* in_sizes, int n_in,
                              void* d_out, int out_size) {
    const float* x          = (const float*)d_in[0];
    const unsigned int* sid = (const unsigned int*)d_in[1]; // int32 or int64
    const float* gamma      = (const float*)d_in[2];
    const float* beta       = (const float*)d_in[3];
    float* out              = (float*)d_out;

    cond_inorm2d_kernel<<<B_DIM * C_DIM, NTHREADS>>>(x, sid, gamma, beta, out);
}

// round 17
// speedup vs baseline: 1.0282x; 1.0282x over previous
#include <cuda_runtime.h>
#include <cuda_bf16.h>
#include <cstdint>

// Shapes (fixed by the problem): B=32, C=256, H=W=64
#define B_DIM 32
#define C_DIM 256
#define HW    4096            // 64*64
#define NTHREADS 256
#define CHUNKS 2              // 2 x 8 floats = 16 floats/thread; 256*16 = 4096

// TERMINAL KERNEL (session R2-R16). Validated model:
//   dur_us = max(floor, kernel + ~4us),  floor ~ 45.1-45.5us (noise +-0.25us)
//   floor  = 268 MB compulsory DRAM traffic / ~5.9 TB/s sustained mixed-R/W.
// Identical binaries measured 45.088 / 45.12 / 45.536 across runs — all
// kernels with mechanical time <= ~41us draw from the same floor
// distribution. All traffic-reduction avenues bench-falsified:
//  - Cross-replay L2 residency: evict_last modifier (thrash at 134MB>126MB),
//    partial pin (neutral), createpolicy fractional (inert), .cs exclusion
//    (DRAM traffic unchanged) — persisting-L2 carve-out is 0 and raising it
//    violates harness device-limit rules.
//  - Width mismatch (v8 ld + v4 st): +5us mechanical (R7/R10/R14 signature).
// Config: width-matched v8/v8, one CTA per (b,c) plane, plane fully
// register-resident (compulsory traffic only), single barrier, fused
// dtype-agnostic style-id decode. Kernel 36.3-37.1us, ~4-5us under the
// floor-relevance threshold.

__device__ __forceinline__ void ld_v8(const float* p, float* v) {
    unsigned r0, r1, r2, r3, r4, r5, r6, r7;
    asm volatile(
        "ld.global.v8.b32 {%0,%1,%2,%3,%4,%5,%6,%7}, [%8];"
        : "=r"(r0), "=r"(r1), "=r"(r2), "=r"(r3),
          "=r"(r4), "=r"(r5), "=r"(r6), "=r"(r7)
        : "l"(p));
    v[0] = __uint_as_float(r0); v[1] = __uint_as_float(r1);
    v[2] = __uint_as_float(r2); v[3] = __uint_as_float(r3);
    v[4] = __uint_as_float(r4); v[5] = __uint_as_float(r5);
    v[6] = __uint_as_float(r6); v[7] = __uint_as_float(r7);
}

__device__ __forceinline__ void st_v8(float* p, const float* v) {
    asm volatile(
        "st.global.v8.b32 [%0], {%1,%2,%3,%4,%5,%6,%7,%8};"
        :
        : "l"(p),
          "r"(__float_as_uint(v[0])), "r"(__float_as_uint(v[1])),
          "r"(__float_as_uint(v[2])), "r"(__float_as_uint(v[3])),
          "r"(__float_as_uint(v[4])), "r"(__float_as_uint(v[5])),
          "r"(__float_as_uint(v[6])), "r"(__float_as_uint(v[7]))
        : "memory");
}

// style_id may arrive as int64 (reference dtype) or int32 (JAX x64-off).
// Thread-0 per-CTA detection over the first 16 words (64 B, in-bounds for
// both layouts): int64 LE with ids in [0,16) => all odd words zero; int32 =>
// odd words random; false-positive prob 16^-8 ~ 2.3e-10.
__global__ __launch_bounds__(NTHREADS, 8)
void cond_inorm2d_kernel(const float* __restrict__ x,
                         const unsigned int* __restrict__ sid_raw,
                         const float* __restrict__ gamma,
                         const float* __restrict__ beta,
                         float* __restrict__ out) {
    const int plane = blockIdx.x;               // b*C + c, 0..8191
    const int b = plane >> 8;                   // C_DIM = 256
    const int c = plane & (C_DIM - 1);

    const float* __restrict__ xp = x   + (size_t)plane * HW;
    float* __restrict__       op = out + (size_t)plane * HW;

    const int t = threadIdx.x;

    __shared__ float sh_s[8];
    __shared__ float sh_s2[8];
    __shared__ int   sh_sid;

    // ---- Thread 0: decode style id (dtype-agnostic) ----
    if (t == 0) {
        unsigned int ored = 0u;
        for (int i = 1; i < 16; i += 2) ored |= sid_raw[i];
        sh_sid = (ored == 0u) ? (int)sid_raw[2 * b] : (int)sid_raw[b];
    }

    // ---- Load entire plane slice into registers; accumulate moments ----
    // Thread t owns 32-byte chunks at float offset (i*NTHREADS + t)*8;
    // fully coalesced, width-matched with the stores below.
    float vf[CHUNKS][8];
    float s = 0.f, s2 = 0.f;
#pragma unroll
    for (int i = 0; i < CHUNKS; i++) {
        ld_v8(xp + (size_t)(i * NTHREADS + t) * 8, vf[i]);
#pragma unroll
        for (int j = 0; j < 8; j++) {
            s  += vf[i][j];
            s2 += vf[i][j] * vf[i][j];
        }
    }

    // ---- Warp reduce ----
#pragma unroll
    for (int o = 16; o > 0; o >>= 1) {
        s  += __shfl_xor_sync(0xFFFFFFFFu, s,  o);
        s2 += __shfl_xor_sync(0xFFFFFFFFu, s2, o);
    }

    const int w = t >> 5, l = t & 31;
    if (l == 0) { sh_s[w] = s; sh_s2[w] = s2; }
    __syncthreads();   // single barrier: partials + sh_sid now visible

    // ---- Every warp redundantly reduces the 8 partials (no 2nd barrier) ----
    float a  = (l < 8) ? sh_s[l]  : 0.f;
    float a2 = (l < 8) ? sh_s2[l] : 0.f;
#pragma unroll
    for (int o = 4; o > 0; o >>= 1) {   // xor 4,2,1 stays within 8-lane group
        a  += __shfl_xor_sync(0xFFFFFFFFu, a,  o);
        a2 += __shfl_xor_sync(0xFFFFFFFFu, a2, o);
    }
    const float tot_s  = __shfl_sync(0xFFFFFFFFu, a,  0);
    const float tot_s2 = __shfl_sync(0xFFFFFFFFu, a2, 0);

    const float inv_n = 1.0f / (float)HW;
    const float mean  = tot_s * inv_n;
    const float var   = fmaxf(tot_s2 * inv_n - mean * mean, 0.0f);
    const float rstd  = rsqrtf(var + 1e-5f);

    const int sid = sh_sid;
    const float g  = gamma[sid * C_DIM + c];
    const float be = beta[sid * C_DIM + c];
    const float sc = g * rstd;
    const float sf = be - mean * sc;     // out = x*sc + sf

    // ---- Normalize from registers and store (width-matched 256-bit) ----
#pragma unroll
    for (int i = 0; i < CHUNKS; i++) {
        float o8[8];
#pragma unroll
        for (int j = 0; j < 8; j++) o8[j] = vf[i][j] * sc + sf;
        st_v8(op + (size_t)(i * NTHREADS + t) * 8, o8);
    }
}

extern "C" void kernel_launch(void* const* d_in, const int* in_sizes, int n_in,
                              void* d_out, int out_size) {
    const float* x          = (const float*)d_in[0];
    const unsigned int* sid = (const unsigned int*)d_in[1]; // int32 or int64
    const float* gamma      = (const float*)d_in[2];
    const float* beta       = (const float*)d_in[3];
    float* out              = (float*)d_out;

    cond_inorm2d_kernel<<<B_DIM * C_DIM, NTHREADS>>>(x, sid, gamma, beta, out);
}